// round 15
// baseline (speedup 1.0000x reference)
#include <cuda_runtime.h>
#include <cuda_fp16.h>
#include <cstdint>
#include <math.h>

#define BDIM 2
#define TLEN 2048
#define CDIM 1024
#define NH   16
#define DH   64
#define MROWS (BDIM * TLEN)   // 4096

// Scratch (allocation-free rule: __device__ globals)
__device__ __half g_qh[(size_t)BDIM * NH * TLEN * DH];   // [B,H,T,Dh], d-permuted, prescaled
__device__ __half g_kh[(size_t)BDIM * NH * TLEN * DH];   // [B,H,T,Dh], d-permuted
__device__ __half g_vth[(size_t)BDIM * NH * DH * TLEN];  // [B,H,Dh,T] transposed, key-permuted
__device__ __half g_atth[(size_t)MROWS * CDIM];          // [B,T,C], C-permuted
__device__ __half g_xh[(size_t)MROWS * CDIM];            // k-permuted
__device__ __half g_wh[4][(size_t)CDIM * CDIM];          // k-permuted

// ============================================================================
// helpers
// ============================================================================
__device__ __forceinline__ void mma_f16(float* d, const uint32_t* a,
                                        const uint32_t* b) {
    asm volatile(
        "mma.sync.aligned.m16n8k16.row.col.f32.f16.f16.f32 "
        "{%0,%1,%2,%3}, {%4,%5,%6,%7}, {%8,%9}, {%0,%1,%2,%3};"
        : "+f"(d[0]), "+f"(d[1]), "+f"(d[2]), "+f"(d[3])
        : "r"(a[0]), "r"(a[1]), "r"(a[2]), "r"(a[3]), "r"(b[0]), "r"(b[1]));
}
__device__ __forceinline__ uint32_t packh2(float lo, float hi) {
    __half2 h = __floats2half2_rn(lo, hi);
    return *(uint32_t*)&h;
}
__device__ __forceinline__ uint32_t smem_u32(const void* p) {
    uint32_t a;
    asm("{ .reg .u64 t; cvta.to.shared.u64 t, %1; cvt.u32.u64 %0, t; }"
        : "=r"(a) : "l"(p));
    return a;
}
__device__ __forceinline__ void cp_async16(uint32_t saddr, const void* gptr) {
    asm volatile("cp.async.ca.shared.global [%0], [%1], 16;"
                 :: "r"(saddr), "l"(gptr) : "memory");
}
__device__ __forceinline__ void cp_commit() {
    asm volatile("cp.async.commit_group;" ::: "memory");
}
// permuted position of logical index c within a 16-block
__device__ __forceinline__ int p16(int c) {
    return 2 * (c & 7) - (c & 1) + 2 * (c >> 3);
}

// ============================================================================
// preround: fp16-convert x and weights, k-permuted within 16-blocks
// ============================================================================
__global__ void __launch_bounds__(256) preround_kernel(
    const float* __restrict__ x,  const float* __restrict__ Wq,
    const float* __restrict__ Wk, const float* __restrict__ Wv,
    const float* __restrict__ Wo)
{
    const int t = blockIdx.y;
    const float* src;
    __half* dst;
    int n;
    if (t == 0) { src = x; dst = g_xh; n = MROWS * CDIM / 4; }
    else {
        src = (t == 1) ? Wq : (t == 2) ? Wk : (t == 3) ? Wv : Wo;
        dst = g_wh[t - 1];
        n = CDIM * CDIM / 4;
    }
    int idx = blockIdx.x * 256 + threadIdx.x;
    if (idx < n) {
        float4 v = ((const float4*)src)[idx];
        int f = idx * 4;
        int c = f & 15;
        size_t blk = ((size_t)(f >> 4)) << 3;
        __half2* d2 = (__half2*)dst;
        d2[blk + (c & 7) + (c >> 3)]             = __floats2half2_rn(v.x, v.y);
        d2[blk + ((c + 2) & 7) + ((c + 2) >> 3)] = __floats2half2_rn(v.z, v.w);
    }
}

// ============================================================================
// fp16 m16n8k16 cp.async 3-stage GEMM — ROUND-13 VERSION (verbatim; the
// round-14 pointer-array refactor regressed it and is reverted).
// ============================================================================
#define BK2 32
#define LDT2H 48
#define STAGES 3
#define NSTEP2 (CDIM / BK2)     // 32
#define GSMEM2 (STAGES * 128 * LDT2H * 2 * 2)   // 73728 B

template <int SCATTER>
__global__ void __launch_bounds__(256, 2) gemm_h_kernel(float* __restrict__ Cout)
{
    extern __shared__ __half smh[];
    const int K = CDIM;
    __half* As = smh;                          // [STAGES][128][LDT2H]
    __half* Ws = smh + STAGES * 128 * LDT2H;

    const __half* Ap = SCATTER ? g_xh : g_atth;
    const __half* W  = g_wh[SCATTER ? blockIdx.z : 3];
    const int z = SCATTER ? blockIdx.z : 3;
    const float oscale = (SCATTER && z == 0) ? 0.125f : 1.0f;

    const int bm0  = blockIdx.y * 128;
    const int bn0  = blockIdx.x * 128;
    const int tid  = threadIdx.x;
    const int lane = tid & 31;
    const int wid  = tid >> 5;
    const int g    = lane >> 2;
    const int tig  = lane & 3;
    const int wm   = (wid & 3) * 32;
    const int wn   = (wid >> 2) * 64;

    const uint32_t sbA = smem_u32(As);
    const uint32_t sbW = smem_u32(Ws);

    float d[2][8][4];
#pragma unroll
    for (int mc = 0; mc < 2; mc++)
#pragma unroll
        for (int nc = 0; nc < 8; nc++)
#pragma unroll
            for (int v = 0; v < 4; v++) d[mc][nc][v] = 0.f;

    auto issue = [&](int t, int slot) {
        const int k0 = t * BK2;
        const uint32_t ab = sbA + (uint32_t)slot * 128 * LDT2H * 2;
        const uint32_t wb = sbW + (uint32_t)slot * 128 * LDT2H * 2;
#pragma unroll
        for (int l = 0; l < 2; l++) {
            int idx = tid + l * 256;      // 0..511
            int r   = idx >> 2;           // 0..127
            int c   = idx & 3;            // 16B chunk (8 halves)
            uint32_t so = (uint32_t)(r * LDT2H + c * 8) * 2;
            cp_async16(ab + so, &Ap[(size_t)(bm0 + r) * K + k0 + c * 8]);
            cp_async16(wb + so, &W [(size_t)(bn0 + r) * K + k0 + c * 8]);
        }
        cp_commit();
    };

    issue(0, 0);
    issue(1, 1);

    for (int s = 0; s < NSTEP2; s++) {
        if (s + 1 < NSTEP2) asm volatile("cp.async.wait_group 1;" ::: "memory");
        else                asm volatile("cp.async.wait_group 0;" ::: "memory");
        __syncthreads();
        if (s + 2 < NSTEP2) issue(s + 2, (s + 2) % STAGES);

        const __half* Ab = As + (s % STAGES) * 128 * LDT2H;
        const __half* Wb = Ws + (s % STAGES) * 128 * LDT2H;
#pragma unroll
        for (int ks = 0; ks < 2; ks++) {
            uint32_t a[2][4];
#pragma unroll
            for (int mc = 0; mc < 2; mc++) {
                int row = wm + mc * 16 + g;
                uint2 lo = *(const uint2*)&Ab[row * LDT2H + ks * 16 + 4 * tig];
                uint2 hi = *(const uint2*)&Ab[(row + 8) * LDT2H + ks * 16 + 4 * tig];
                a[mc][0] = lo.x; a[mc][1] = hi.x; a[mc][2] = lo.y; a[mc][3] = hi.y;
            }
#pragma unroll
            for (int nc = 0; nc < 8; nc++) {
                uint2 bb = *(const uint2*)&Wb[(wn + nc * 8 + g) * LDT2H + ks * 16 + 4 * tig];
                uint32_t b[2] = {bb.x, bb.y};
                mma_f16(d[0][nc], a[0], b);
                mma_f16(d[1][nc], a[1], b);
            }
        }
    }

#pragma unroll
    for (int mc = 0; mc < 2; mc++) {
#pragma unroll
        for (int nc = 0; nc < 8; nc++) {
            int n = bn0 + wn + nc * 8 + tig * 2;
#pragma unroll
            for (int rr = 0; rr < 2; rr++) {
                int m = bm0 + wm + mc * 16 + g + rr * 8;
                float v0 = d[mc][nc][rr * 2 + 0];
                float v1 = d[mc][nc][rr * 2 + 1];
                if (SCATTER) {
                    v0 *= oscale; v1 *= oscale;
                    int bb = m >> 11;
                    int tt = m & 2047;
                    int hh = n >> 6;
                    int dd = n & 63;                 // even
                    if (z < 2) {
                        __half* base = (z == 0 ? g_qh : g_kh)
                            + (((size_t)bb * NH + hh) * TLEN + tt) * DH;
                        int r16 = dd & 15;
                        ((__half2*)base)[(dd >> 4) * 8 + (r16 & 7) + (r16 >> 3)]
                            = __floats2half2_rn(v0, v1);
                    } else {
                        int tperm = (tt & ~15) + p16(tt & 15);
                        __half* base = g_vth + ((size_t)bb * NH + hh) * DH * TLEN;
                        base[(size_t)dd * TLEN + tperm]       = __float2half_rn(v0);
                        base[(size_t)(dd + 1) * TLEN + tperm] = __float2half_rn(v1);
                    }
                } else {
                    *(float2*)&Cout[(size_t)m * CDIM + n] = make_float2(v0, v1);
                }
            }
        }
    }
}

// ============================================================================
// fp16 m16n8k16 causal flash attention — Q fragments in registers,
// 3-stage cp.async KV ring (wait_group 1), exact boundary-tile mask-skip
// (nc_lim / j_lim; skipped blocks contribute exact zeros).
// smem: 3 stages x (K 64x80 + V 64x80) halves = 61440 B -> 2 CTAs/SM.
// ============================================================================
#define LDAH 80
#define QROWS 128
#define KVSTAGEH (2 * 64 * LDAH)        // halves per stage = 10240
#define ATT_SMEM (3 * KVSTAGEH * 2)     // 61440 B

__global__ void __launch_bounds__(256, 2) attn_h_kernel()
{
    extern __shared__ __half smh[];
    __half* kvb = smh;                       // [3][ K[64][LDAH] | V[64][LDAH] ]
    const uint32_t skv = smem_u32(kvb);

    const int qt = (gridDim.x - 1) - blockIdx.x;   // big tiles first
    const int bh = blockIdx.y;
    const __half* qg = g_qh + (size_t)bh * TLEN * DH;
    const __half* kg = g_kh + (size_t)bh * TLEN * DH;
    const __half* vg = g_vth + (size_t)bh * DH * TLEN;  // [d][t]

    const int tid  = threadIdx.x;
    const int lane = tid & 31;
    const int wid  = tid >> 5;
    const int g    = lane >> 2;
    const int tig  = lane & 3;

    const int wrow = qt * QROWS + wid * 16;

    // ---- Q fragments: kt-invariant, straight from global to registers ----
    uint32_t qa[4][4];
#pragma unroll
    for (int j = 0; j < 4; j++) {
        uint2 q0 = *(const uint2*)&qg[(size_t)(wrow + g) * DH + 16 * j + 4 * tig];
        uint2 q1 = *(const uint2*)&qg[(size_t)(wrow + g + 8) * DH + 16 * j + 4 * tig];
        qa[j][0] = q0.x; qa[j][1] = q1.x; qa[j][2] = q0.y; qa[j][3] = q1.y;
    }

    // ---- cp.async state (pointer increments) ----
    const int r = tid >> 3;                 // 0..31
    const int c = tid & 7;                  // 16B chunk
    const __half* pK0 = kg + (size_t)r * DH + c * 8;
    const __half* pK1 = kg + (size_t)(r + 32) * DH + c * 8;
    const __half* pV0 = vg + (size_t)r * TLEN + c * 8;
    const __half* pV1 = vg + (size_t)(r + 32) * TLEN + c * 8;
    const uint32_t sKo0 = (uint32_t)(r * LDAH + c * 8) * 2;
    const uint32_t sKo1 = (uint32_t)((r + 32) * LDAH + c * 8) * 2;
    uint32_t skvS[3];
#pragma unroll
    for (int i = 0; i < 3; i++) skvS[i] = skv + (uint32_t)i * KVSTAGEH * 2;

    auto issue_kv = [&](int slot) {
        const uint32_t kb = skvS[slot];
        const uint32_t vb = kb + (uint32_t)(64 * LDAH) * 2;
        cp_async16(kb + sKo0, pK0);
        cp_async16(kb + sKo1, pK1);
        cp_async16(vb + sKo0, pV0);
        cp_async16(vb + sKo1, pV1);
        pK0 += (size_t)64 * DH; pK1 += (size_t)64 * DH;
        pV0 += 64;              pV1 += 64;
        cp_commit();
    };

    const int ktmax = 2 * qt + 1;           // >= 1 always
    issue_kv(0);
    issue_kv(1);

    float mrow0 = -INFINITY, mrow1 = -INFINITY;
    float lrow0 = 0.f, lrow1 = 0.f;
    float o[8][4];
#pragma unroll
    for (int nc = 0; nc < 8; nc++)
#pragma unroll
        for (int v = 0; v < 4; v++) o[nc][v] = 0.f;

    const int oK = g * LDAH + 4 * tig;      // fragment base offset (K and V)

    int st = 0, sti = 2;
    for (int kt = 0; kt <= ktmax; kt++) {
        if (kt < ktmax) asm volatile("cp.async.wait_group 1;" ::: "memory");
        else            asm volatile("cp.async.wait_group 0;" ::: "memory");
        __syncthreads();
        if (kt + 2 <= ktmax) {
            issue_kv(sti);
            sti = (sti + 1 == 3) ? 0 : sti + 1;
        }

        const __half* ks = kvb + st * KVSTAGEH;
        const __half* vs = ks + 64 * LDAH;
        st = (st + 1 == 3) ? 0 : st + 1;

        if (kt * 64 <= wrow + 15) {
            // exact skip bounds for fully-masked blocks (warp-uniform)
            const int rem = wrow + 15 - kt * 64;     // >= 0 here
            int nc_lim = (rem >> 3) + 1; if (nc_lim > 8) nc_lim = 8;
            int j_lim  = (rem >> 4) + 1; if (j_lim  > 4) j_lim  = 4;

            // ---- S = Q K^T ----
            float s[8][4];
#pragma unroll
            for (int nc = 0; nc < 8; nc++)
#pragma unroll
                for (int v = 0; v < 4; v++) s[nc][v] = 0.f;
#pragma unroll
            for (int j = 0; j < 4; j++) {
#pragma unroll
                for (int nc = 0; nc < 8; nc++) {
                    if (nc < nc_lim) {
                        uint2 bk = *(const uint2*)&ks[oK + nc * 8 * LDAH + 16 * j];
                        uint32_t b[2] = {bk.x, bk.y};
                        mma_f16(s[nc], qa[j], b);
                    }
                }
            }

            // ---- causal mask ----
            if (kt * 64 + 63 > wrow) {
#pragma unroll
                for (int nc = 0; nc < 8; nc++) {
                    int col = kt * 64 + nc * 8 + 2 * tig;
                    if (col     > wrow + g)     s[nc][0] = -INFINITY;
                    if (col + 1 > wrow + g)     s[nc][1] = -INFINITY;
                    if (col     > wrow + g + 8) s[nc][2] = -INFINITY;
                    if (col + 1 > wrow + g + 8) s[nc][3] = -INFINITY;
                }
            }

            // ---- warp-local online softmax ----
            float t0 = -INFINITY, t1 = -INFINITY;
#pragma unroll
            for (int nc = 0; nc < 8; nc++) {
                t0 = fmaxf(t0, fmaxf(s[nc][0], s[nc][1]));
                t1 = fmaxf(t1, fmaxf(s[nc][2], s[nc][3]));
            }
            t0 = fmaxf(t0, __shfl_xor_sync(0xffffffffu, t0, 1));
            t0 = fmaxf(t0, __shfl_xor_sync(0xffffffffu, t0, 2));
            t1 = fmaxf(t1, __shfl_xor_sync(0xffffffffu, t1, 1));
            t1 = fmaxf(t1, __shfl_xor_sync(0xffffffffu, t1, 2));
            float mn0 = fmaxf(mrow0, t0);
            float mn1 = fmaxf(mrow1, t1);
            float sc0 = __expf(mrow0 - mn0);
            float sc1 = __expf(mrow1 - mn1);
            mrow0 = mn0; mrow1 = mn1;

            float rs0 = 0.f, rs1 = 0.f;
#pragma unroll
            for (int nc = 0; nc < 8; nc++) {
                s[nc][0] = __expf(s[nc][0] - mn0);
                s[nc][1] = __expf(s[nc][1] - mn0);
                s[nc][2] = __expf(s[nc][2] - mn1);
                s[nc][3] = __expf(s[nc][3] - mn1);
                rs0 += s[nc][0] + s[nc][1];
                rs1 += s[nc][2] + s[nc][3];
            }
            rs0 += __shfl_xor_sync(0xffffffffu, rs0, 1);
            rs0 += __shfl_xor_sync(0xffffffffu, rs0, 2);
            rs1 += __shfl_xor_sync(0xffffffffu, rs1, 1);
            rs1 += __shfl_xor_sync(0xffffffffu, rs1, 2);
            lrow0 = lrow0 * sc0 + rs0;
            lrow1 = lrow1 * sc1 + rs1;
#pragma unroll
            for (int nc = 0; nc < 8; nc++) {
                o[nc][0] *= sc0; o[nc][1] *= sc0;
                o[nc][2] *= sc1; o[nc][3] *= sc1;
            }

            // ---- O += P V (skip fully-masked key blocks: P there is 0) ----
#pragma unroll
            for (int j = 0; j < 4; j++) {
                if (j < j_lim) {
                    uint32_t a[4];
                    a[0] = packh2(s[2 * j][0],     s[2 * j][1]);
                    a[1] = packh2(s[2 * j][2],     s[2 * j][3]);
                    a[2] = packh2(s[2 * j + 1][0], s[2 * j + 1][1]);
                    a[3] = packh2(s[2 * j + 1][2], s[2 * j + 1][3]);
#pragma unroll
                    for (int nc = 0; nc < 8; nc++) {
                        uint2 bv = *(const uint2*)&vs[oK + nc * 8 * LDAH + 16 * j];
                        uint32_t b[2] = {bv.x, bv.y};
                        mma_f16(o[nc], a, b);
                    }
                }
            }
        }
    }

    // normalize, write g_atth [B,T,C] half, C permuted within 16-blocks
    const int b = bh >> 4;
    const int h = bh & 15;
    const float inv0 = 1.f / lrow0;
    const float inv1 = 1.f / lrow1;
    const int t0r = wrow + g;
    const int t1r = wrow + g + 8;
#pragma unroll
    for (int nc = 0; nc < 8; nc++) {
        int dd  = h * DH + nc * 8 + 2 * tig;    // even
        int r16 = dd & 15;
        int h2i = (dd >> 4) * 8 + (r16 & 7) + (r16 >> 3);
        ((__half2*)&g_atth[((size_t)b * TLEN + t0r) * CDIM])[h2i]
            = __floats2half2_rn(o[nc][0] * inv0, o[nc][1] * inv0);
        ((__half2*)&g_atth[((size_t)b * TLEN + t1r) * CDIM])[h2i]
            = __floats2half2_rn(o[nc][2] * inv1, o[nc][3] * inv1);
    }
}

// ----------------------------------------------------------------------------
extern "C" void kernel_launch(void* const* d_in, const int* in_sizes, int n_in,
                              void* d_out, int out_size)
{
    const float* x  = (const float*)d_in[0];
    const float* Wq = (const float*)d_in[1];
    const float* Wk = (const float*)d_in[2];
    const float* Wv = (const float*)d_in[3];
    const float* Wo = (const float*)d_in[4];
    float* out = (float*)d_out;

    preround_kernel<<<dim3(4096, 5), 256>>>(x, Wq, Wk, Wv, Wo);

    cudaFuncSetAttribute(gemm_h_kernel<1>,
                         cudaFuncAttributeMaxDynamicSharedMemorySize, GSMEM2);
    cudaFuncSetAttribute(gemm_h_kernel<0>,
                         cudaFuncAttributeMaxDynamicSharedMemorySize, GSMEM2);

    gemm_h_kernel<1><<<dim3(CDIM / 128, MROWS / 128, 3), 256, GSMEM2>>>(nullptr);

    cudaFuncSetAttribute(attn_h_kernel,
                         cudaFuncAttributeMaxDynamicSharedMemorySize, ATT_SMEM);
    attn_h_kernel<<<dim3(TLEN / QROWS, BDIM * NH), 256, ATT_SMEM>>>();

    gemm_h_kernel<0><<<dim3(CDIM / 128, MROWS / 128, 1), 256, GSMEM2>>>(out);
}

// round 16
// speedup vs baseline: 1.5757x; 1.5757x over previous
#include <cuda_runtime.h>
#include <cuda_fp16.h>
#include <cstdint>
#include <math.h>

#define BDIM 2
#define TLEN 2048
#define CDIM 1024
#define NH   16
#define DH   64
#define MROWS (BDIM * TLEN)   // 4096

// Scratch (allocation-free rule: __device__ globals)
// halves; k-dims permuted within 16-blocks by p16 (see below)
__device__ __half g_qh[(size_t)BDIM * NH * TLEN * DH];   // [B,H,T,Dh], d-permuted, prescaled
__device__ __half g_kh[(size_t)BDIM * NH * TLEN * DH];   // [B,H,T,Dh], d-permuted
__device__ __half g_vth[(size_t)BDIM * NH * DH * TLEN];  // [B,H,Dh,T] transposed, key-permuted
__device__ __half g_atth[(size_t)MROWS * CDIM];          // [B,T,C], C-permuted
__device__ __half g_xh[(size_t)MROWS * CDIM];            // k-permuted
__device__ __half g_wh[4][(size_t)CDIM * CDIM];          // k-permuted

// ============================================================================
// helpers
// ============================================================================
__device__ __forceinline__ void mma_f16(float* d, const uint32_t* a,
                                        const uint32_t* b) {
    asm volatile(
        "mma.sync.aligned.m16n8k16.row.col.f32.f16.f16.f32 "
        "{%0,%1,%2,%3}, {%4,%5,%6,%7}, {%8,%9}, {%0,%1,%2,%3};"
        : "+f"(d[0]), "+f"(d[1]), "+f"(d[2]), "+f"(d[3])
        : "r"(a[0]), "r"(a[1]), "r"(a[2]), "r"(a[3]), "r"(b[0]), "r"(b[1]));
}
__device__ __forceinline__ uint32_t packh2(float lo, float hi) {
    __half2 h = __floats2half2_rn(lo, hi);
    return *(uint32_t*)&h;
}
__device__ __forceinline__ uint32_t smem_u32(const void* p) {
    uint32_t a;
    asm("{ .reg .u64 t; cvta.to.shared.u64 t, %1; cvt.u32.u64 %0, t; }"
        : "=r"(a) : "l"(p));
    return a;
}
__device__ __forceinline__ void cp_async16(uint32_t saddr, const void* gptr) {
    asm volatile("cp.async.ca.shared.global [%0], [%1], 16;"
                 :: "r"(saddr), "l"(gptr) : "memory");
}
__device__ __forceinline__ void cp_commit() {
    asm volatile("cp.async.commit_group;" ::: "memory");
}
// permuted position of logical index c within a 16-block:
// positions 4t..4t+3 hold logical {2t, 2t+1, 2t+8, 2t+9}
__device__ __forceinline__ int p16(int c) {
    return 2 * (c & 7) - (c & 1) + 2 * (c >> 3);
}

// ============================================================================
// preround: fp16-convert x and weights, k-permuted within 16-blocks
// ============================================================================
__global__ void __launch_bounds__(256) preround_kernel(
    const float* __restrict__ x,  const float* __restrict__ Wq,
    const float* __restrict__ Wk, const float* __restrict__ Wv,
    const float* __restrict__ Wo)
{
    const int t = blockIdx.y;
    const float* src;
    __half* dst;
    int n;
    if (t == 0) { src = x; dst = g_xh; n = MROWS * CDIM / 4; }
    else {
        src = (t == 1) ? Wq : (t == 2) ? Wk : (t == 3) ? Wv : Wo;
        dst = g_wh[t - 1];
        n = CDIM * CDIM / 4;
    }
    int idx = blockIdx.x * 256 + threadIdx.x;
    if (idx < n) {
        float4 v = ((const float4*)src)[idx];
        int f = idx * 4;
        int c = f & 15;                       // 0,4,8,12
        size_t blk = ((size_t)(f >> 4)) << 3; // half2 base of 16-block
        __half2* d2 = (__half2*)dst;
        d2[blk + (c & 7) + (c >> 3)]                 = __floats2half2_rn(v.x, v.y);
        d2[blk + ((c + 2) & 7) + ((c + 2) >> 3)]     = __floats2half2_rn(v.z, v.w);
    }
}

// ============================================================================
// fp16 m16n8k16 cp.async 3-stage GEMM: C[m,n] = sum_k A[m,k] * W[n,k]
// CTA 128x128, BK=32 (2 k16-steps), 8 warps (4x2), warp tile 32x64.
// SCATTER=1: z=0 -> q (prescaled 0.125, d-permuted half), z=1 -> k (d-perm),
//            z=2 -> v (transposed [d][t], key-permuted).
// SCATTER=0: fp32 out.
// ============================================================================
#define BK2 32
#define LDT2H 48
#define STAGES 3
#define NSTEP2 (CDIM / BK2)     // 32
#define GSMEM2 (STAGES * 128 * LDT2H * 2 * 2)   // 73728 B

template <int SCATTER>
__global__ void __launch_bounds__(256, 2) gemm_h_kernel(float* __restrict__ Cout)
{
    extern __shared__ __half smh[];
    const int K = CDIM;
    __half* As = smh;                          // [STAGES][128][LDT2H]
    __half* Ws = smh + STAGES * 128 * LDT2H;

    const __half* Ap = SCATTER ? g_xh : g_atth;
    const __half* W  = g_wh[SCATTER ? blockIdx.z : 3];
    const int z = SCATTER ? blockIdx.z : 3;
    const float oscale = (SCATTER && z == 0) ? 0.125f : 1.0f;

    const int bm0  = blockIdx.y * 128;
    const int bn0  = blockIdx.x * 128;
    const int tid  = threadIdx.x;
    const int lane = tid & 31;
    const int wid  = tid >> 5;
    const int g    = lane >> 2;
    const int tig  = lane & 3;
    const int wm   = (wid & 3) * 32;
    const int wn   = (wid >> 2) * 64;

    const uint32_t sbA = smem_u32(As);
    const uint32_t sbW = smem_u32(Ws);

    float d[2][8][4];
#pragma unroll
    for (int mc = 0; mc < 2; mc++)
#pragma unroll
        for (int nc = 0; nc < 8; nc++)
#pragma unroll
            for (int v = 0; v < 4; v++) d[mc][nc][v] = 0.f;

    auto issue = [&](int t, int slot) {
        const int k0 = t * BK2;
        const uint32_t ab = sbA + (uint32_t)slot * 128 * LDT2H * 2;
        const uint32_t wb = sbW + (uint32_t)slot * 128 * LDT2H * 2;
#pragma unroll
        for (int l = 0; l < 2; l++) {
            int idx = tid + l * 256;      // 0..511
            int r   = idx >> 2;           // 0..127
            int c   = idx & 3;            // 16B chunk (8 halves)
            uint32_t so = (uint32_t)(r * LDT2H + c * 8) * 2;
            cp_async16(ab + so, &Ap[(size_t)(bm0 + r) * K + k0 + c * 8]);
            cp_async16(wb + so, &W [(size_t)(bn0 + r) * K + k0 + c * 8]);
        }
        cp_commit();
    };

    issue(0, 0);
    issue(1, 1);

    for (int s = 0; s < NSTEP2; s++) {
        if (s + 1 < NSTEP2) asm volatile("cp.async.wait_group 1;" ::: "memory");
        else                asm volatile("cp.async.wait_group 0;" ::: "memory");
        __syncthreads();
        if (s + 2 < NSTEP2) issue(s + 2, (s + 2) % STAGES);

        const __half* Ab = As + (s % STAGES) * 128 * LDT2H;
        const __half* Wb = Ws + (s % STAGES) * 128 * LDT2H;
#pragma unroll
        for (int ks = 0; ks < 2; ks++) {
            uint32_t a[2][4];
#pragma unroll
            for (int mc = 0; mc < 2; mc++) {
                int row = wm + mc * 16 + g;
                uint2 lo = *(const uint2*)&Ab[row * LDT2H + ks * 16 + 4 * tig];
                uint2 hi = *(const uint2*)&Ab[(row + 8) * LDT2H + ks * 16 + 4 * tig];
                a[mc][0] = lo.x; a[mc][1] = hi.x; a[mc][2] = lo.y; a[mc][3] = hi.y;
            }
#pragma unroll
            for (int nc = 0; nc < 8; nc++) {
                uint2 bb = *(const uint2*)&Wb[(wn + nc * 8 + g) * LDT2H + ks * 16 + 4 * tig];
                uint32_t b[2] = {bb.x, bb.y};
                mma_f16(d[0][nc], a[0], b);
                mma_f16(d[1][nc], a[1], b);
            }
        }
    }

#pragma unroll
    for (int mc = 0; mc < 2; mc++) {
#pragma unroll
        for (int nc = 0; nc < 8; nc++) {
            int n = bn0 + wn + nc * 8 + tig * 2;
#pragma unroll
            for (int rr = 0; rr < 2; rr++) {
                int m = bm0 + wm + mc * 16 + g + rr * 8;
                float v0 = d[mc][nc][rr * 2 + 0];
                float v1 = d[mc][nc][rr * 2 + 1];
                if (SCATTER) {
                    v0 *= oscale; v1 *= oscale;
                    int bb = m >> 11;
                    int tt = m & 2047;
                    int hh = n >> 6;
                    int dd = n & 63;                 // even
                    if (z < 2) {
                        // q/k: [B,H,T,Dh] half, d permuted within 16-blocks
                        __half* base = (z == 0 ? g_qh : g_kh)
                            + (((size_t)bb * NH + hh) * TLEN + tt) * DH;
                        int r16 = dd & 15;
                        ((__half2*)base)[(dd >> 4) * 8 + (r16 & 7) + (r16 >> 3)]
                            = __floats2half2_rn(v0, v1);
                    } else {
                        // v: transposed [B,H,Dh,T], key (t) permuted
                        int tperm = (tt & ~15) + p16(tt & 15);
                        __half* base = g_vth + ((size_t)bb * NH + hh) * DH * TLEN;
                        base[(size_t)dd * TLEN + tperm]       = __float2half_rn(v0);
                        base[(size_t)(dd + 1) * TLEN + tperm] = __float2half_rn(v1);
                    }
                } else {
                    *(float2*)&Cout[(size_t)m * CDIM + n] = make_float2(v0, v1);
                }
            }
        }
    }
}

// ============================================================================
// fp16 m16n8k16 causal flash attention — register-resident P,
// double-buffered cp.async K/V, all fragment loads LDS.64 via permuted layout.
// smem halves: Q 128x80, per stage K 64x80 + V 64x80. 61440 B -> 2 CTAs/SM.
// ============================================================================
#define LDAH 80
#define QROWS 128
#define KVSTAGEH (2 * 64 * LDAH)        // halves per K+V stage = 10240
#define ATT_SMEM ((QROWS * LDAH + 2 * KVSTAGEH) * 2)   // 61440 B

__global__ void __launch_bounds__(256, 2) attn_h_kernel()
{
    extern __shared__ __half smh[];
    __half* qs  = smh;                       // [128][LDAH] (perm d)
    __half* kvb = qs + QROWS * LDAH;         // [2][ K[64][LDAH] | V[64][LDAH] ]
    const uint32_t sq  = smem_u32(qs);
    const uint32_t skv = smem_u32(kvb);

    const int qt = (gridDim.x - 1) - blockIdx.x;   // big tiles first
    const int bh = blockIdx.y;
    const __half* qg = g_qh + (size_t)bh * TLEN * DH;
    const __half* kg = g_kh + (size_t)bh * TLEN * DH;
    const __half* vg = g_vth + (size_t)bh * DH * TLEN;  // [d][t]

    const int tid  = threadIdx.x;
    const int lane = tid & 31;
    const int wid  = tid >> 5;
    const int g    = lane >> 2;
    const int tig  = lane & 3;

    auto issue_kv = [&](int kt, int b) {
        const uint32_t kb = skv + (uint32_t)(b * KVSTAGEH) * 2;
        const uint32_t vb = kb + (uint32_t)(64 * LDAH) * 2;
#pragma unroll
        for (int l = 0; l < 2; l++) {
            int idx = tid + l * 256;        // 0..511
            int r   = idx >> 3;             // 0..63
            int c   = idx & 7;              // 16B chunk (8 halves)
            cp_async16(kb + (uint32_t)(r * LDAH + c * 8) * 2,
                       &kg[(size_t)(kt * 64 + r) * DH + c * 8]);
            cp_async16(vb + (uint32_t)(r * LDAH + c * 8) * 2,
                       &vg[(size_t)r * TLEN + kt * 64 + c * 8]);
        }
        cp_commit();
    };

    // group 0: Q tile (1024 chunks) + K/V tile 0
#pragma unroll
    for (int l = 0; l < 4; l++) {
        int idx = tid + l * 256;
        int r   = idx >> 3;                 // 0..127
        int c   = idx & 7;
        cp_async16(sq + (uint32_t)(r * LDAH + c * 8) * 2,
                   &qg[(size_t)(qt * QROWS + r) * DH + c * 8]);
    }
    issue_kv(0, 0);

    const int wrow = qt * QROWS + wid * 16;
    float mrow0 = -INFINITY, mrow1 = -INFINITY;
    float lrow0 = 0.f, lrow1 = 0.f;
    float o[8][4];
#pragma unroll
    for (int nc = 0; nc < 8; nc++)
#pragma unroll
        for (int v = 0; v < 4; v++) o[nc][v] = 0.f;

    const int ktmax = 2 * qt + 1;
    for (int kt = 0; kt <= ktmax; kt++) {
        asm volatile("cp.async.wait_group 0;" ::: "memory");
        __syncthreads();
        if (kt < ktmax) issue_kv(kt + 1, (kt + 1) & 1);

        const __half* ks = kvb + (kt & 1) * KVSTAGEH;
        const __half* vs = ks + 64 * LDAH;

        if (kt * 64 <= wrow + 15) {
            // ---- S = Q K^T (4 k16-steps over Dh=64) ----
            float s[8][4];
#pragma unroll
            for (int nc = 0; nc < 8; nc++)
#pragma unroll
                for (int v = 0; v < 4; v++) s[nc][v] = 0.f;
#pragma unroll
            for (int j = 0; j < 4; j++) {
                uint2 q0 = *(const uint2*)&qs[(wid * 16 + g) * LDAH + 16 * j + 4 * tig];
                uint2 q1 = *(const uint2*)&qs[(wid * 16 + g + 8) * LDAH + 16 * j + 4 * tig];
                uint32_t a[4] = {q0.x, q1.x, q0.y, q1.y};
#pragma unroll
                for (int nc = 0; nc < 8; nc++) {
                    uint2 bk = *(const uint2*)&ks[(nc * 8 + g) * LDAH + 16 * j + 4 * tig];
                    uint32_t b[2] = {bk.x, bk.y};
                    mma_f16(s[nc], a, b);
                }
            }

            // ---- causal mask ----
            if (kt * 64 + 63 > wrow) {
#pragma unroll
                for (int nc = 0; nc < 8; nc++) {
                    int col = kt * 64 + nc * 8 + 2 * tig;
                    if (col     > wrow + g)     s[nc][0] = -INFINITY;
                    if (col + 1 > wrow + g)     s[nc][1] = -INFINITY;
                    if (col     > wrow + g + 8) s[nc][2] = -INFINITY;
                    if (col + 1 > wrow + g + 8) s[nc][3] = -INFINITY;
                }
            }

            // ---- warp-local online softmax ----
            float t0 = -INFINITY, t1 = -INFINITY;
#pragma unroll
            for (int nc = 0; nc < 8; nc++) {
                t0 = fmaxf(t0, fmaxf(s[nc][0], s[nc][1]));
                t1 = fmaxf(t1, fmaxf(s[nc][2], s[nc][3]));
            }
            t0 = fmaxf(t0, __shfl_xor_sync(0xffffffffu, t0, 1));
            t0 = fmaxf(t0, __shfl_xor_sync(0xffffffffu, t0, 2));
            t1 = fmaxf(t1, __shfl_xor_sync(0xffffffffu, t1, 1));
            t1 = fmaxf(t1, __shfl_xor_sync(0xffffffffu, t1, 2));
            float mn0 = fmaxf(mrow0, t0);
            float mn1 = fmaxf(mrow1, t1);
            float sc0 = __expf(mrow0 - mn0);
            float sc1 = __expf(mrow1 - mn1);
            mrow0 = mn0; mrow1 = mn1;

            float rs0 = 0.f, rs1 = 0.f;
#pragma unroll
            for (int nc = 0; nc < 8; nc++) {
                s[nc][0] = __expf(s[nc][0] - mn0);
                s[nc][1] = __expf(s[nc][1] - mn0);
                s[nc][2] = __expf(s[nc][2] - mn1);
                s[nc][3] = __expf(s[nc][3] - mn1);
                rs0 += s[nc][0] + s[nc][1];
                rs1 += s[nc][2] + s[nc][3];
            }
            rs0 += __shfl_xor_sync(0xffffffffu, rs0, 1);
            rs0 += __shfl_xor_sync(0xffffffffu, rs0, 2);
            rs1 += __shfl_xor_sync(0xffffffffu, rs1, 1);
            rs1 += __shfl_xor_sync(0xffffffffu, rs1, 2);
            lrow0 = lrow0 * sc0 + rs0;
            lrow1 = lrow1 * sc1 + rs1;
#pragma unroll
            for (int nc = 0; nc < 8; nc++) {
                o[nc][0] *= sc0; o[nc][1] *= sc0;
                o[nc][2] *= sc1; o[nc][3] *= sc1;
            }

            // ---- O += P V : A packed from softmax regs, B = V^T LDS.64 ----
#pragma unroll
            for (int j = 0; j < 4; j++) {
                uint32_t a[4];
                a[0] = packh2(s[2 * j][0],     s[2 * j][1]);
                a[1] = packh2(s[2 * j][2],     s[2 * j][3]);
                a[2] = packh2(s[2 * j + 1][0], s[2 * j + 1][1]);
                a[3] = packh2(s[2 * j + 1][2], s[2 * j + 1][3]);
#pragma unroll
                for (int nc = 0; nc < 8; nc++) {
                    uint2 bv = *(const uint2*)&vs[(nc * 8 + g) * LDAH + 16 * j + 4 * tig];
                    uint32_t b[2] = {bv.x, bv.y};
                    mma_f16(o[nc], a, b);
                }
            }
        }
    }

    // normalize, write g_atth [B,T,C] half, C permuted within 16-blocks
    const int b = bh >> 4;
    const int h = bh & 15;
    const float inv0 = 1.f / lrow0;
    const float inv1 = 1.f / lrow1;
    const int t0r = wrow + g;
    const int t1r = wrow + g + 8;
#pragma unroll
    for (int nc = 0; nc < 8; nc++) {
        int dd  = h * DH + nc * 8 + 2 * tig;    // even
        int r16 = dd & 15;
        int h2i = (dd >> 4) * 8 + (r16 & 7) + (r16 >> 3);
        ((__half2*)&g_atth[((size_t)b * TLEN + t0r) * CDIM])[h2i]
            = __floats2half2_rn(o[nc][0] * inv0, o[nc][1] * inv0);
        ((__half2*)&g_atth[((size_t)b * TLEN + t1r) * CDIM])[h2i]
            = __floats2half2_rn(o[nc][2] * inv1, o[nc][3] * inv1);
    }
}

// ----------------------------------------------------------------------------
extern "C" void kernel_launch(void* const* d_in, const int* in_sizes, int n_in,
                              void* d_out, int out_size)
{
    const float* x  = (const float*)d_in[0];
    const float* Wq = (const float*)d_in[1];
    const float* Wk = (const float*)d_in[2];
    const float* Wv = (const float*)d_in[3];
    const float* Wo = (const float*)d_in[4];
    float* out = (float*)d_out;

    preround_kernel<<<dim3(4096, 5), 256>>>(x, Wq, Wk, Wv, Wo);

    cudaFuncSetAttribute(gemm_h_kernel<1>,
                         cudaFuncAttributeMaxDynamicSharedMemorySize, GSMEM2);
    cudaFuncSetAttribute(gemm_h_kernel<0>,
                         cudaFuncAttributeMaxDynamicSharedMemorySize, GSMEM2);

    gemm_h_kernel<1><<<dim3(CDIM / 128, MROWS / 128, 3), 256, GSMEM2>>>(nullptr);

    cudaFuncSetAttribute(attn_h_kernel,
                         cudaFuncAttributeMaxDynamicSharedMemorySize, ATT_SMEM);
    attn_h_kernel<<<dim3(TLEN / QROWS, BDIM * NH), 256, ATT_SMEM>>>();

    gemm_h_kernel<0><<<dim3(CDIM / 128, MROWS / 128, 1), 256, GSMEM2>>>(out);
}

// round 17
// speedup vs baseline: 1.7987x; 1.1415x over previous
#include <cuda_runtime.h>
#include <cuda_fp16.h>
#include <cstdint>
#include <math.h>

#define BDIM 2
#define TLEN 2048
#define CDIM 1024
#define NH   16
#define DH   64
#define MROWS (BDIM * TLEN)   // 4096

// Scratch (allocation-free rule: __device__ globals) — ALL PLAIN LAYOUTS now
// (ldmatrix handles fragment distribution; no permutations needed).
__device__ __half g_qh[(size_t)BDIM * NH * TLEN * DH];   // [B,H,T,Dh], prescaled 0.125
__device__ __half g_kh[(size_t)BDIM * NH * TLEN * DH];   // [B,H,T,Dh]
__device__ __half g_vh[(size_t)BDIM * NH * TLEN * DH];   // [B,H,T,Dh]
__device__ __half g_atth[(size_t)MROWS * CDIM];          // [B,T,C]
__device__ __half g_xh[(size_t)MROWS * CDIM];
__device__ __half g_wh[4][(size_t)CDIM * CDIM];

// ============================================================================
// helpers
// ============================================================================
__device__ __forceinline__ void mma_f16(float* d, const uint32_t* a,
                                        const uint32_t* b) {
    asm volatile(
        "mma.sync.aligned.m16n8k16.row.col.f32.f16.f16.f32 "
        "{%0,%1,%2,%3}, {%4,%5,%6,%7}, {%8,%9}, {%0,%1,%2,%3};"
        : "+f"(d[0]), "+f"(d[1]), "+f"(d[2]), "+f"(d[3])
        : "r"(a[0]), "r"(a[1]), "r"(a[2]), "r"(a[3]), "r"(b[0]), "r"(b[1]));
}
__device__ __forceinline__ void ldsm_x4(uint32_t* r, uint32_t addr) {
    asm volatile("ldmatrix.sync.aligned.m8n8.x4.shared.b16 {%0,%1,%2,%3}, [%4];"
                 : "=r"(r[0]), "=r"(r[1]), "=r"(r[2]), "=r"(r[3]) : "r"(addr));
}
__device__ __forceinline__ void ldsm_x4t(uint32_t* r, uint32_t addr) {
    asm volatile("ldmatrix.sync.aligned.m8n8.x4.trans.shared.b16 {%0,%1,%2,%3}, [%4];"
                 : "=r"(r[0]), "=r"(r[1]), "=r"(r[2]), "=r"(r[3]) : "r"(addr));
}
__device__ __forceinline__ uint32_t packh2(float lo, float hi) {
    __half2 h = __floats2half2_rn(lo, hi);
    return *(uint32_t*)&h;
}
__device__ __forceinline__ uint32_t smem_u32(const void* p) {
    uint32_t a;
    asm("{ .reg .u64 t; cvta.to.shared.u64 t, %1; cvt.u32.u64 %0, t; }"
        : "=r"(a) : "l"(p));
    return a;
}
__device__ __forceinline__ void cp_async16(uint32_t saddr, const void* gptr) {
    asm volatile("cp.async.ca.shared.global [%0], [%1], 16;"
                 :: "r"(saddr), "l"(gptr) : "memory");
}
__device__ __forceinline__ void cp_commit() {
    asm volatile("cp.async.commit_group;" ::: "memory");
}

// ============================================================================
// preround: fp16-convert x and weights (plain layout)
// ============================================================================
__global__ void __launch_bounds__(256) preround_kernel(
    const float* __restrict__ x,  const float* __restrict__ Wq,
    const float* __restrict__ Wk, const float* __restrict__ Wv,
    const float* __restrict__ Wo)
{
    const int t = blockIdx.y;
    const float* src;
    __half* dst;
    int n;
    if (t == 0) { src = x; dst = g_xh; n = MROWS * CDIM / 4; }
    else {
        src = (t == 1) ? Wq : (t == 2) ? Wk : (t == 3) ? Wv : Wo;
        dst = g_wh[t - 1];
        n = CDIM * CDIM / 4;
    }
    int idx = blockIdx.x * 256 + threadIdx.x;
    if (idx < n) {
        float4 v = ((const float4*)src)[idx];
        __half2* d2 = (__half2*)dst;
        d2[idx * 2 + 0] = __floats2half2_rn(v.x, v.y);
        d2[idx * 2 + 1] = __floats2half2_rn(v.z, v.w);
    }
}

// ============================================================================
// fp16 m16n8k16 cp.async 3-stage GEMM with ldmatrix fragment loads.
// CTA 128x128, BK=32, 8 warps (4x2), warp tile 32x64.
// SCATTER=1: z selects q (scaled 0.125) / k / v, all plain [B,H,T,Dh] half.
// SCATTER=0: fp32 out.
// ============================================================================
#define BK2 32
#define LDT2H 40
#define STAGES 3
#define NSTEP2 (CDIM / BK2)     // 32
#define GSMEM2 (STAGES * 128 * LDT2H * 2 * 2)   // 61440 B

template <int SCATTER>
__global__ void __launch_bounds__(256, 2) gemm_h_kernel(float* __restrict__ Cout)
{
    extern __shared__ __half smh[];
    const int K = CDIM;
    __half* As = smh;                          // [STAGES][128][LDT2H]
    __half* Ws = smh + STAGES * 128 * LDT2H;

    const __half* Ap = SCATTER ? g_xh : g_atth;
    const __half* W  = g_wh[SCATTER ? blockIdx.z : 3];
    const int z = SCATTER ? blockIdx.z : 3;
    const float oscale = (SCATTER && z == 0) ? 0.125f : 1.0f;

    const int bm0  = blockIdx.y * 128;
    const int bn0  = blockIdx.x * 128;
    const int tid  = threadIdx.x;
    const int lane = tid & 31;
    const int wid  = tid >> 5;
    const int g    = lane >> 2;
    const int tig  = lane & 3;
    const int wm   = (wid & 3) * 32;
    const int wn   = (wid >> 2) * 64;

    const uint32_t sbA = smem_u32(As);
    const uint32_t sbW = smem_u32(Ws);

    // per-lane ldmatrix offsets (relative to stage base), hoisted
    // A x4: lanes 0-15 -> rows wm+(lane&15), k lo; lanes 16-31 -> same rows, k+8
    const uint32_t offA = (uint32_t)((wm + (lane & 15)) * LDT2H + (lane >> 4) * 8) * 2;
    // B x4 (two nc per load): rows wn+(lane&7)+((lane>>4)&1)*8, k half ((lane>>3)&1)*8
    const uint32_t offB = (uint32_t)((wn + (lane & 7) + ((lane >> 4) & 1) * 8) * LDT2H
                                     + ((lane >> 3) & 1) * 8) * 2;

    float d[2][8][4];
#pragma unroll
    for (int mc = 0; mc < 2; mc++)
#pragma unroll
        for (int nc = 0; nc < 8; nc++)
#pragma unroll
            for (int v = 0; v < 4; v++) d[mc][nc][v] = 0.f;

    auto issue = [&](int t, int slot) {
        const int k0 = t * BK2;
        const uint32_t ab = sbA + (uint32_t)slot * 128 * LDT2H * 2;
        const uint32_t wb = sbW + (uint32_t)slot * 128 * LDT2H * 2;
#pragma unroll
        for (int l = 0; l < 2; l++) {
            int idx = tid + l * 256;      // 0..511
            int r   = idx >> 2;           // 0..127
            int c   = idx & 3;            // 16B chunk (8 halves)
            uint32_t so = (uint32_t)(r * LDT2H + c * 8) * 2;
            cp_async16(ab + so, &Ap[(size_t)(bm0 + r) * K + k0 + c * 8]);
            cp_async16(wb + so, &W [(size_t)(bn0 + r) * K + k0 + c * 8]);
        }
        cp_commit();
    };

    issue(0, 0);
    issue(1, 1);

    for (int s = 0; s < NSTEP2; s++) {
        if (s + 1 < NSTEP2) asm volatile("cp.async.wait_group 1;" ::: "memory");
        else                asm volatile("cp.async.wait_group 0;" ::: "memory");
        __syncthreads();
        if (s + 2 < NSTEP2) issue(s + 2, (s + 2) % STAGES);

        const uint32_t stA = sbA + (uint32_t)(s % STAGES) * 128 * LDT2H * 2 + offA;
        const uint32_t stB = sbW + (uint32_t)(s % STAGES) * 128 * LDT2H * 2 + offB;
#pragma unroll
        for (int ks = 0; ks < 2; ks++) {
            uint32_t a[2][4];
            ldsm_x4(a[0], stA + ks * 32);
            ldsm_x4(a[1], stA + 16 * LDT2H * 2 + ks * 32);
#pragma unroll
            for (int p = 0; p < 4; p++) {
                uint32_t b[4];
                ldsm_x4(b, stB + (uint32_t)p * 16 * LDT2H * 2 + ks * 32);
                mma_f16(d[0][2 * p],     a[0], b);
                mma_f16(d[1][2 * p],     a[1], b);
                mma_f16(d[0][2 * p + 1], a[0], b + 2);
                mma_f16(d[1][2 * p + 1], a[1], b + 2);
            }
        }
    }

#pragma unroll
    for (int mc = 0; mc < 2; mc++) {
#pragma unroll
        for (int nc = 0; nc < 8; nc++) {
            int n = bn0 + wn + nc * 8 + tig * 2;
#pragma unroll
            for (int rr = 0; rr < 2; rr++) {
                int m = bm0 + wm + mc * 16 + g + rr * 8;
                float v0 = d[mc][nc][rr * 2 + 0];
                float v1 = d[mc][nc][rr * 2 + 1];
                if (SCATTER) {
                    v0 *= oscale; v1 *= oscale;
                    int bb = m >> 11;
                    int tt = m & 2047;
                    int hh = n >> 6;
                    int dd = n & 63;                 // even
                    __half* base = (z == 0 ? g_qh : (z == 1 ? g_kh : g_vh))
                        + (((size_t)bb * NH + hh) * TLEN + tt) * DH;
                    ((__half2*)base)[dd >> 1] = __floats2half2_rn(v0, v1);
                } else {
                    *(float2*)&Cout[(size_t)m * CDIM + n] = make_float2(v0, v1);
                }
            }
        }
    }
}

// ============================================================================
// fp16 m16n8k16 causal flash attention — ldmatrix fragments, Q frags hoisted
// out of the kt-loop, register-resident P, double-buffered cp.async K/V.
// V kept in natural [T,Dh] layout; PV B-fragments via ldmatrix.trans.
// smem halves: Q 128x72 + 2 stages x (K 64x72 + V 64x72) = 55296 B.
// ============================================================================
#define LDAH 72
#define QROWS 128
#define KVSTAGEH (2 * 64 * LDAH)        // halves per K+V stage = 9216
#define ATT_SMEM ((QROWS * LDAH + 2 * KVSTAGEH) * 2)   // 55296 B

__global__ void __launch_bounds__(256, 2) attn_h_kernel()
{
    extern __shared__ __half smh[];
    __half* qs  = smh;                       // [128][LDAH]
    __half* kvb = qs + QROWS * LDAH;         // [2][ K[64][LDAH] | V[64][LDAH] ]
    const uint32_t sq  = smem_u32(qs);
    const uint32_t skv = smem_u32(kvb);

    const int qt = (gridDim.x - 1) - blockIdx.x;   // big tiles first
    const int bh = blockIdx.y;
    const __half* qg = g_qh + (size_t)bh * TLEN * DH;
    const __half* kg = g_kh + (size_t)bh * TLEN * DH;
    const __half* vg = g_vh + (size_t)bh * TLEN * DH;

    const int tid  = threadIdx.x;
    const int lane = tid & 31;
    const int wid  = tid >> 5;
    const int g    = lane >> 2;
    const int tig  = lane & 3;

    auto issue_kv = [&](int kt, int b) {
        const uint32_t kb = skv + (uint32_t)(b * KVSTAGEH) * 2;
        const uint32_t vb = kb + (uint32_t)(64 * LDAH) * 2;
#pragma unroll
        for (int l = 0; l < 2; l++) {
            int idx = tid + l * 256;        // 0..511
            int r   = idx >> 3;             // 0..63
            int c   = idx & 7;              // 16B chunk (8 halves)
            uint32_t so = (uint32_t)(r * LDAH + c * 8) * 2;
            cp_async16(kb + so, &kg[(size_t)(kt * 64 + r) * DH + c * 8]);
            cp_async16(vb + so, &vg[(size_t)(kt * 64 + r) * DH + c * 8]);
        }
        cp_commit();
    };

    // group 0: Q tile (1024 chunks) + K/V tile 0
#pragma unroll
    for (int l = 0; l < 4; l++) {
        int idx = tid + l * 256;
        int r   = idx >> 3;                 // 0..127
        int c   = idx & 7;
        cp_async16(sq + (uint32_t)(r * LDAH + c * 8) * 2,
                   &qg[(size_t)(qt * QROWS + r) * DH + c * 8]);
    }
    issue_kv(0, 0);

    const int wrow = qt * QROWS + wid * 16;
    float mrow0 = -INFINITY, mrow1 = -INFINITY;
    float lrow0 = 0.f, lrow1 = 0.f;
    float o[8][4];
#pragma unroll
    for (int nc = 0; nc < 8; nc++)
#pragma unroll
        for (int v = 0; v < 4; v++) o[nc][v] = 0.f;

    // per-lane ldmatrix offsets
    // Q (A frag, x4): rows wid*16+(lane&15), k half (lane>>4)*8
    const uint32_t offQ = (uint32_t)((wid * 16 + (lane & 15)) * LDAH + (lane >> 4) * 8) * 2;
    // K (B frag, x4, two nc): rows (lane&7)+((lane>>4)&1)*8, k half ((lane>>3)&1)*8
    const uint32_t offK = (uint32_t)(((lane & 7) + ((lane >> 4) & 1) * 8) * LDAH
                                     + ((lane >> 3) & 1) * 8) * 2;
    // V (B frag via trans, x4, two nc): rows t=(lane&15), d col 8*((lane>>4)&1)
    const uint32_t offV = (uint32_t)((lane & 15) * LDAH + ((lane >> 4) & 1) * 8) * 2;

    uint32_t qa[4][4];   // Q fragments, loaded once at kt==0

    const int ktmax = 2 * qt + 1;
    for (int kt = 0; kt <= ktmax; kt++) {
        asm volatile("cp.async.wait_group 0;" ::: "memory");
        __syncthreads();
        if (kt < ktmax) issue_kv(kt + 1, (kt + 1) & 1);

        if (kt == 0) {
#pragma unroll
            for (int j = 0; j < 4; j++) ldsm_x4(qa[j], sq + offQ + j * 32);
        }

        const uint32_t ksb = skv + (uint32_t)((kt & 1) * KVSTAGEH) * 2;
        const uint32_t vsb = ksb + (uint32_t)(64 * LDAH) * 2;

        if (kt * 64 <= wrow + 15) {
            // ---- S = Q K^T ----
            float s[8][4];
#pragma unroll
            for (int nc = 0; nc < 8; nc++)
#pragma unroll
                for (int v = 0; v < 4; v++) s[nc][v] = 0.f;
#pragma unroll
            for (int j = 0; j < 4; j++) {
#pragma unroll
                for (int p = 0; p < 4; p++) {
                    uint32_t b[4];
                    ldsm_x4(b, ksb + offK + (uint32_t)p * 16 * LDAH * 2 + j * 32);
                    mma_f16(s[2 * p],     qa[j], b);
                    mma_f16(s[2 * p + 1], qa[j], b + 2);
                }
            }

            // ---- causal mask ----
            if (kt * 64 + 63 > wrow) {
#pragma unroll
                for (int nc = 0; nc < 8; nc++) {
                    int col = kt * 64 + nc * 8 + 2 * tig;
                    if (col     > wrow + g)     s[nc][0] = -INFINITY;
                    if (col + 1 > wrow + g)     s[nc][1] = -INFINITY;
                    if (col     > wrow + g + 8) s[nc][2] = -INFINITY;
                    if (col + 1 > wrow + g + 8) s[nc][3] = -INFINITY;
                }
            }

            // ---- warp-local online softmax ----
            float t0 = -INFINITY, t1 = -INFINITY;
#pragma unroll
            for (int nc = 0; nc < 8; nc++) {
                t0 = fmaxf(t0, fmaxf(s[nc][0], s[nc][1]));
                t1 = fmaxf(t1, fmaxf(s[nc][2], s[nc][3]));
            }
            t0 = fmaxf(t0, __shfl_xor_sync(0xffffffffu, t0, 1));
            t0 = fmaxf(t0, __shfl_xor_sync(0xffffffffu, t0, 2));
            t1 = fmaxf(t1, __shfl_xor_sync(0xffffffffu, t1, 1));
            t1 = fmaxf(t1, __shfl_xor_sync(0xffffffffu, t1, 2));
            float mn0 = fmaxf(mrow0, t0);
            float mn1 = fmaxf(mrow1, t1);
            float sc0 = __expf(mrow0 - mn0);
            float sc1 = __expf(mrow1 - mn1);
            mrow0 = mn0; mrow1 = mn1;

            float rs0 = 0.f, rs1 = 0.f;
#pragma unroll
            for (int nc = 0; nc < 8; nc++) {
                s[nc][0] = __expf(s[nc][0] - mn0);
                s[nc][1] = __expf(s[nc][1] - mn0);
                s[nc][2] = __expf(s[nc][2] - mn1);
                s[nc][3] = __expf(s[nc][3] - mn1);
                rs0 += s[nc][0] + s[nc][1];
                rs1 += s[nc][2] + s[nc][3];
            }
            rs0 += __shfl_xor_sync(0xffffffffu, rs0, 1);
            rs0 += __shfl_xor_sync(0xffffffffu, rs0, 2);
            rs1 += __shfl_xor_sync(0xffffffffu, rs1, 1);
            rs1 += __shfl_xor_sync(0xffffffffu, rs1, 2);
            lrow0 = lrow0 * sc0 + rs0;
            lrow1 = lrow1 * sc1 + rs1;
#pragma unroll
            for (int nc = 0; nc < 8; nc++) {
                o[nc][0] *= sc0; o[nc][1] *= sc0;
                o[nc][2] *= sc1; o[nc][3] *= sc1;
            }

            // ---- O += P V : A packed from softmax regs, B via ldmatrix.trans ----
#pragma unroll
            for (int j = 0; j < 4; j++) {
                uint32_t a[4];
                a[0] = packh2(s[2 * j][0],     s[2 * j][1]);
                a[1] = packh2(s[2 * j][2],     s[2 * j][3]);
                a[2] = packh2(s[2 * j + 1][0], s[2 * j + 1][1]);
                a[3] = packh2(s[2 * j + 1][2], s[2 * j + 1][3]);
#pragma unroll
                for (int p = 0; p < 4; p++) {
                    uint32_t b[4];
                    ldsm_x4t(b, vsb + offV + (uint32_t)j * 16 * LDAH * 2 + p * 32);
                    mma_f16(o[2 * p],     a, b);
                    mma_f16(o[2 * p + 1], a, b + 2);
                }
            }
        }
    }

    // normalize, write g_atth [B,T,C] half (plain)
    const int b = bh >> 4;
    const int h = bh & 15;
    const float inv0 = 1.f / lrow0;
    const float inv1 = 1.f / lrow1;
    const int t0r = wrow + g;
    const int t1r = wrow + g + 8;
#pragma unroll
    for (int nc = 0; nc < 8; nc++) {
        int dd = h * DH + nc * 8 + 2 * tig;     // even
        ((__half2*)&g_atth[((size_t)b * TLEN + t0r) * CDIM])[dd >> 1]
            = __floats2half2_rn(o[nc][0] * inv0, o[nc][1] * inv0);
        ((__half2*)&g_atth[((size_t)b * TLEN + t1r) * CDIM])[dd >> 1]
            = __floats2half2_rn(o[nc][2] * inv1, o[nc][3] * inv1);
    }
}

// ----------------------------------------------------------------------------
extern "C" void kernel_launch(void* const* d_in, const int* in_sizes, int n_in,
                              void* d_out, int out_size)
{
    const float* x  = (const float*)d_in[0];
    const float* Wq = (const float*)d_in[1];
    const float* Wk = (const float*)d_in[2];
    const float* Wv = (const float*)d_in[3];
    const float* Wo = (const float*)d_in[4];
    float* out = (float*)d_out;

    preround_kernel<<<dim3(4096, 5), 256>>>(x, Wq, Wk, Wv, Wo);

    cudaFuncSetAttribute(gemm_h_kernel<1>,
                         cudaFuncAttributeMaxDynamicSharedMemorySize, GSMEM2);
    cudaFuncSetAttribute(gemm_h_kernel<0>,
                         cudaFuncAttributeMaxDynamicSharedMemorySize, GSMEM2);

    gemm_h_kernel<1><<<dim3(CDIM / 128, MROWS / 128, 3), 256, GSMEM2>>>(nullptr);

    cudaFuncSetAttribute(attn_h_kernel,
                         cudaFuncAttributeMaxDynamicSharedMemorySize, ATT_SMEM);
    attn_h_kernel<<<dim3(TLEN / QROWS, BDIM * NH), 256, ATT_SMEM>>>();

    gemm_h_kernel<0><<<dim3(CDIM / 128, MROWS / 128, 1), 256, GSMEM2>>>(out);
}